// round 15
// baseline (speedup 1.0000x reference)
#include <cuda_runtime.h>
#include <cuda.h>

// LocalSpatialEncoding: enc=[rel(3),|rel|] -> (W1,BN,ReLU)[4] -> (W2,BN,ReLU)[8]
// B=8,N=16384,K=16. Output (B,N,K,8) fp32.
// R15 (= R14 with the swizzle bug fixed PROPERLY):
//   per-16B-slot swizzled addresses computed exactly: slot s of row `lane`
//   lands at s ^ (lane&7). No in-pair adjacency assumption, no fixup pass.
//   4 points/thread; warp = 128 pts = 4KB SW128 tile; one tensor.2d TMA
//   store per warp. 15 weight LDS.128 amortized over 4 points.
// Fallback: R8-style kernel if tensor-map encode is unavailable.

#define LSE_EPS 1e-5f
#define TOTAL   (8 * 16384 * 16)   // 2097152 points
#define THREADS 256
#define WARPS   8
#define PPT     4                  // points per thread

__device__ __forceinline__ float sqrt_ap(float x) {
    float r; asm("sqrt.approx.f32 %0,%1;" : "=f"(r) : "f"(x)); return r;
}
__device__ __forceinline__ unsigned smem_u32(const void* p) {
    unsigned a;
    asm("{ .reg .u64 t; cvta.to.shared.u64 t, %1; cvt.u32.u64 %0, t; }"
        : "=r"(a) : "l"(p));
    return a;
}

__device__ __forceinline__ void fold_weights(
    float* sw, int t,
    const float* W1, const float* g1, const float* b1, const float* m1, const float* v1,
    const float* W2, const float* g2, const float* b2, const float* m2, const float* v2)
{
    if (t < 16) {
        int o = t >> 2;
        float s = g1[o] * rsqrtf(v1[o] + LSE_EPS);
        sw[t] = W1[t] * s;
        if ((t & 3) == 0) sw[16 + o] = b1[o] - m1[o] * s;
    } else if (t < 48) {
        int i = t - 16;
        int o = i >> 2;
        float s = g2[o] * rsqrtf(v2[o] + LSE_EPS);
        sw[20 + i] = W2[i] * s;
        if ((i & 3) == 0) sw[52 + o] = b2[o] - m2[o] * s;
    }
}

// MLP for one point; stages the 8 outputs as two 16B slots at EXACT swizzled
// addresses dst0/dst1 (computed by the caller).
__device__ __forceinline__ void mlp_point_store(
    float rx, float ry, float rz, const float4* w4,
    const float* t1p, const float* t2p0, const float* t2p1,
    unsigned dst0, unsigned dst1)
{
    float d = sqrt_ap(fmaf(rx, rx, fmaf(ry, ry, rz * rz)));
    float h[4];
#pragma unroll
    for (int o = 0; o < 4; o++) {
        float4 w = w4[o];
        h[o] = fmaxf(fmaf(rx, w.x, fmaf(ry, w.y, fmaf(rz, w.z, fmaf(d, w.w, t1p[o])))), 0.0f);
    }
    float yv[8];
#pragma unroll
    for (int o = 0; o < 8; o++) {
        float4 w = w4[5 + o];
        float bias = (o < 4) ? t2p0[o] : t2p1[o - 4];
        yv[o] = fmaxf(fmaf(h[0], w.x, fmaf(h[1], w.y, fmaf(h[2], w.z, fmaf(h[3], w.w, bias)))), 0.0f);
    }
    asm volatile("st.shared.v4.f32 [%0], {%1,%2,%3,%4};"
                 :: "r"(dst0), "f"(yv[0]), "f"(yv[1]), "f"(yv[2]), "f"(yv[3]) : "memory");
    asm volatile("st.shared.v4.f32 [%0], {%1,%2,%3,%4};"
                 :: "r"(dst1), "f"(yv[4]), "f"(yv[5]), "f"(yv[6]), "f"(yv[7]) : "memory");
}

// ---------------- R15: TMA tensor-store kernel ------------------------------
__global__ void __launch_bounds__(THREADS)
lse_tma(const float* __restrict__ coords,
        const float* __restrict__ nbr,
        const float* __restrict__ W1, const float* __restrict__ g1,
        const float* __restrict__ b1, const float* __restrict__ m1,
        const float* __restrict__ v1,
        const float* __restrict__ W2, const float* __restrict__ g2,
        const float* __restrict__ b2, const float* __restrict__ m2,
        const float* __restrict__ v2,
        const __grid_constant__ CUtensorMap tmap)
{
    __shared__ __align__(16) float sw[60];
    __shared__ char raw[WARPS * 4096 + 1024];   // over-allocated for 1KB alignment

    int t = threadIdx.x;
    fold_weights(sw, t, W1, g1, b1, m1, v1, W2, g2, b2, m2, v2);
    __syncthreads();
    const float4* w4 = reinterpret_cast<const float4*>(sw);

    float4 t1v = w4[4];
    const float* t1p = reinterpret_cast<const float*>(&t1v);
    float4 t2a = w4[13], t2b = w4[14];
    const float* t2p0 = reinterpret_cast<const float*>(&t2a);
    const float* t2p1 = reinterpret_cast<const float*>(&t2b);

    int q    = blockIdx.x * THREADS + t;   // thread owns points 4q..4q+3
    int warp = t >> 5;
    int lane = t & 31;

    // ---- Loads: 12 neighbor floats = 3 x LDG.128 contiguous & coalesced ----
    const float4* nb4 = reinterpret_cast<const float4*>(nbr) + (size_t)q * 3;
    float4 va = __ldg(nb4 + 0);
    float4 vb = __ldg(nb4 + 1);
    float4 vc = __ldg(nb4 + 2);

    // Center: all 4 points share one center (4 | 16); 4 consecutive threads broadcast.
    const float* cp = coords + (size_t)(q >> 2) * 3;
    float c0 = __ldg(cp + 0), c1 = __ldg(cp + 1), c2 = __ldg(cp + 2);

    // 1024B-aligned stage base; warp tile = 4KB (stays 1KB aligned).
    unsigned stg  = (smem_u32(raw) + 1023u) & ~1023u;
    unsigned tile = stg + warp * 4096u;

    // Lane owns 128B row `lane`. SW128: 16B slot s lands at slot s ^ (lane&7).
    unsigned rowb = tile + 128u * lane;
    unsigned m    = lane & 7u;
    // Exact swizzled slot addresses for the 8 slots (2 per point).
#define SLOT(s) (rowb + 16u * ((unsigned)(s) ^ m))

    // ---- 4 points, computed and staged one at a time ----
    // pt0=(va.x,va.y,va.z) pt1=(va.w,vb.x,vb.y) pt2=(vb.z,vb.w,vc.x) pt3=(vc.y,vc.z,vc.w)
    mlp_point_store(va.x - c0, va.y - c1, va.z - c2, w4, t1p, t2p0, t2p1, SLOT(0), SLOT(1));
    mlp_point_store(va.w - c0, vb.x - c1, vb.y - c2, w4, t1p, t2p0, t2p1, SLOT(2), SLOT(3));
    mlp_point_store(vb.z - c0, vb.w - c1, vc.x - c2, w4, t1p, t2p0, t2p1, SLOT(4), SLOT(5));
    mlp_point_store(vc.y - c0, vc.z - c1, vc.w - c2, w4, t1p, t2p0, t2p1, SLOT(6), SLOT(7));
#undef SLOT

    asm volatile("fence.proxy.async.shared::cta;" ::: "memory");
    __syncwarp();

    if (lane == 0) {
        int row = (blockIdx.x * WARPS + warp) * 32;   // 32 gmem rows of 128B per warp
        const CUtensorMap* tp = &tmap;
        asm volatile(
            "cp.async.bulk.tensor.2d.global.shared::cta.tile.bulk_group "
            "[%0, {%1, %2}], [%3];"
            :: "l"(tp), "r"(0), "r"(row), "r"(tile) : "memory");
        asm volatile("cp.async.bulk.commit_group;" ::: "memory");
        asm volatile("cp.async.bulk.wait_group.read 0;" ::: "memory");
    }
}

// ---------------- Fallback: R8-style kernel (2 pts/thread, STG path) --------
#define STR 68
__global__ void __launch_bounds__(THREADS)
lse_r8(const float* __restrict__ coords,
       const float* __restrict__ nbr,
       const float* __restrict__ W1, const float* __restrict__ g1,
       const float* __restrict__ b1, const float* __restrict__ m1,
       const float* __restrict__ v1,
       const float* __restrict__ W2, const float* __restrict__ g2,
       const float* __restrict__ b2, const float* __restrict__ m2,
       const float* __restrict__ v2,
       float* __restrict__ out)
{
    __shared__ __align__(16) float sw[60];
    __shared__ __align__(16) float sbuf[WARPS][8][STR];

    int t = threadIdx.x;
    fold_weights(sw, t, W1, g1, b1, m1, v1, W2, g2, b2, m2, v2);
    __syncthreads();
    const float4* w4 = reinterpret_cast<const float4*>(sw);

    float4 t1v = w4[4];
    const float* t1p = reinterpret_cast<const float*>(&t1v);
    float4 t2a = w4[13], t2b = w4[14];
    const float* t2p0 = reinterpret_cast<const float*>(&t2a);
    const float* t2p1 = reinterpret_cast<const float*>(&t2b);

    int g    = blockIdx.x * THREADS + t;
    int warp = t >> 5;
    int lane = t & 31;

    const float2* nb2 = reinterpret_cast<const float2*>(nbr) + (size_t)g * 3;
    float2 va = __ldg(nb2 + 0);
    float2 vb = __ldg(nb2 + 1);
    float2 vc = __ldg(nb2 + 2);
    const float* cp = coords + (size_t)(g >> 3) * 3;
    float c0 = __ldg(cp + 0), c1 = __ldg(cp + 1), c2 = __ldg(cp + 2);

    float ax = va.x - c0, ay = va.y - c1, az = vb.x - c2;
    float bx = vb.y - c0, by = vc.x - c1, bz = vc.y - c2;
    float da = sqrt_ap(fmaf(ax, ax, fmaf(ay, ay, az * az)));
    float db = sqrt_ap(fmaf(bx, bx, fmaf(by, by, bz * bz)));

    float ha[4], hb[4];
#pragma unroll
    for (int o = 0; o < 4; o++) {
        float4 w = w4[o];
        ha[o] = fmaxf(fmaf(ax, w.x, fmaf(ay, w.y, fmaf(az, w.z, fmaf(da, w.w, t1p[o])))), 0.0f);
        hb[o] = fmaxf(fmaf(bx, w.x, fmaf(by, w.y, fmaf(bz, w.z, fmaf(db, w.w, t1p[o])))), 0.0f);
    }
#pragma unroll
    for (int o = 0; o < 8; o++) {
        float4 w = w4[5 + o];
        float bias = (o < 4) ? t2p0[o] : t2p1[o - 4];
        float ya = fmaxf(fmaf(ha[0], w.x, fmaf(ha[1], w.y, fmaf(ha[2], w.z, fmaf(ha[3], w.w, bias)))), 0.0f);
        float yb = fmaxf(fmaf(hb[0], w.x, fmaf(hb[1], w.y, fmaf(hb[2], w.z, fmaf(hb[3], w.w, bias)))), 0.0f);
        *reinterpret_cast<float2*>(&sbuf[warp][o][2 * lane]) = make_float2(ya, yb);
    }
    __syncwarp();

    int warpbase = blockIdx.x * (THREADS * 2) + warp * 64;
    float4* o4 = reinterpret_cast<float4*>(out) + (size_t)warpbase * 2;
#pragma unroll
    for (int k = 0; k < 4; k++) {
        int f  = lane + 32 * k;
        int pt = f >> 1;
        int cb = (f & 1) * 4;
        float4 v;
        v.x = sbuf[warp][cb + 0][pt];
        v.y = sbuf[warp][cb + 1][pt];
        v.z = sbuf[warp][cb + 2][pt];
        v.w = sbuf[warp][cb + 3][pt];
        o4[f] = v;
    }
}

// ---------------- host ------------------------------------------------------
typedef CUresult (*tmap_encode_fn)(
    CUtensorMap*, CUtensorMapDataType, cuuint32_t, void*,
    const cuuint64_t*, const cuuint64_t*, const cuuint32_t*, const cuuint32_t*,
    CUtensorMapInterleave, CUtensorMapSwizzle, CUtensorMapL2promotion,
    CUtensorMapFloatOOBfill);

extern "C" void kernel_launch(void* const* d_in, const int* in_sizes, int n_in,
                              void* d_out, int out_size)
{
    const float* coords = (const float*)d_in[0];
    const float* nbr    = (const float*)d_in[1];
    const float* W1     = (const float*)d_in[2];
    const float* g1     = (const float*)d_in[3];
    const float* b1     = (const float*)d_in[4];
    const float* m1     = (const float*)d_in[5];
    const float* v1     = (const float*)d_in[6];
    const float* W2     = (const float*)d_in[7];
    const float* g2     = (const float*)d_in[8];
    const float* b2     = (const float*)d_in[9];
    const float* m2     = (const float*)d_in[10];
    const float* v2     = (const float*)d_in[11];
    float* out = (float*)d_out;

    tmap_encode_fn encode = nullptr;
    cudaDriverEntryPointQueryResult qr = cudaDriverEntryPointSymbolNotFound;
#if CUDART_VERSION >= 12050
    cudaGetDriverEntryPointByVersion("cuTensorMapEncodeTiled", (void**)&encode,
                                     12000, cudaEnableDefault, &qr);
#else
    cudaGetDriverEntryPoint("cuTensorMapEncodeTiled", (void**)&encode,
                            cudaEnableDefault, &qr);
#endif

    bool tma_ok = false;
    CUtensorMap tmap;
    if (encode && qr == cudaDriverEntryPointSuccess) {
        cuuint64_t dims[2]    = {32, (cuuint64_t)TOTAL * 32 / 128};  // 524288 rows
        cuuint64_t strides[1] = {128};
        cuuint32_t box[2]     = {32, 32};     // one warp tile: 32 rows x 128B = 4KB
        cuuint32_t es[2]      = {1, 1};
        CUresult r = encode(&tmap, CU_TENSOR_MAP_DATA_TYPE_FLOAT32, 2, out,
                            dims, strides, box, es,
                            CU_TENSOR_MAP_INTERLEAVE_NONE,
                            CU_TENSOR_MAP_SWIZZLE_128B,
                            CU_TENSOR_MAP_L2_PROMOTION_L2_128B,
                            CU_TENSOR_MAP_FLOAT_OOB_FILL_NONE);
        tma_ok = (r == CUDA_SUCCESS);
    }

    if (tma_ok) {
        int blocks = TOTAL / (THREADS * PPT);   // 2048
        lse_tma<<<blocks, THREADS>>>(coords, nbr, W1, g1, b1, m1, v1,
                                     W2, g2, b2, m2, v2, tmap);
    } else {
        int blocks = TOTAL / (THREADS * 2);     // 4096
        lse_r8<<<blocks, THREADS>>>(coords, nbr, W1, g1, b1, m1, v1,
                                    W2, g2, b2, m2, v2, out);
    }
}

// round 16
// speedup vs baseline: 1.1085x; 1.1085x over previous
#include <cuda_runtime.h>
#include <cuda.h>

// LocalSpatialEncoding: enc=[rel(3),|rel|] -> (W1,BN,ReLU)[4] -> (W2,BN,ReLU)[8]
// B=8,N=16384,K=16. Output (B,N,K,8) fp32.
// R16: R13's proven 2-pt/thread compute + staging, run TWICE per thread
// (sequential passes, no cross-pass register liveness):
//   - block prologue (weight fold + sync) amortized over 1024 pts
//   - pass-0 data LDGs issued BEFORE weight fold (latency overlap)
//   - warp = 128 pts = 4KB SW128 tile (2 x R13 half-tiles), ONE tensor.2d store
// Fallback: R8-style kernel if tensor-map encode is unavailable.

#define LSE_EPS 1e-5f
#define TOTAL   (8 * 16384 * 16)   // 2097152 points
#define THREADS 256
#define WARPS   8

__device__ __forceinline__ float sqrt_ap(float x) {
    float r; asm("sqrt.approx.f32 %0,%1;" : "=f"(r) : "f"(x)); return r;
}
__device__ __forceinline__ unsigned smem_u32(const void* p) {
    unsigned a;
    asm("{ .reg .u64 t; cvta.to.shared.u64 t, %1; cvt.u32.u64 %0, t; }"
        : "=r"(a) : "l"(p));
    return a;
}

__device__ __forceinline__ void fold_weights(
    float* sw, int t,
    const float* W1, const float* g1, const float* b1, const float* m1, const float* v1,
    const float* W2, const float* g2, const float* b2, const float* m2, const float* v2)
{
    if (t < 16) {
        int o = t >> 2;
        float s = g1[o] * rsqrtf(v1[o] + LSE_EPS);
        sw[t] = W1[t] * s;
        if ((t & 3) == 0) sw[16 + o] = b1[o] - m1[o] * s;
    } else if (t < 48) {
        int i = t - 16;
        int o = i >> 2;
        float s = g2[o] * rsqrtf(v2[o] + LSE_EPS);
        sw[20 + i] = W2[i] * s;
        if ((i & 3) == 0) sw[52 + o] = b2[o] - m2[o] * s;
    }
}

// R13's proven 2-point MLP + SW128 staging, for 2-pt index gp, staged into
// the 2KB half-tile at smem address `half` (1KB-aligned).
__device__ __forceinline__ void two_points_pass(
    float2 va, float2 vb, float2 vc, float c0, float c1, float c2,
    const float4* w4, const float* t1p, const float* t2p0, const float* t2p1,
    unsigned half, int lane)
{
    // pt0 = (va.x, va.y, vb.x), pt1 = (vb.y, vc.x, vc.y)
    float ax = va.x - c0, ay = va.y - c1, az = vb.x - c2;
    float bx = vb.y - c0, by = vc.x - c1, bz = vc.y - c2;
    float da = sqrt_ap(fmaf(ax, ax, fmaf(ay, ay, az * az)));
    float db = sqrt_ap(fmaf(bx, bx, fmaf(by, by, bz * bz)));

    float ha[4], hb[4];
#pragma unroll
    for (int o = 0; o < 4; o++) {
        float4 w = w4[o];
        ha[o] = fmaxf(fmaf(ax, w.x, fmaf(ay, w.y, fmaf(az, w.z, fmaf(da, w.w, t1p[o])))), 0.0f);
        hb[o] = fmaxf(fmaf(bx, w.x, fmaf(by, w.y, fmaf(bz, w.z, fmaf(db, w.w, t1p[o])))), 0.0f);
    }
    float ya[8], yb[8];
#pragma unroll
    for (int o = 0; o < 8; o++) {
        float4 w = w4[5 + o];
        float bias = (o < 4) ? t2p0[o] : t2p1[o - 4];
        ya[o] = fmaxf(fmaf(ha[0], w.x, fmaf(ha[1], w.y, fmaf(ha[2], w.z, fmaf(ha[3], w.w, bias)))), 0.0f);
        yb[o] = fmaxf(fmaf(hb[0], w.x, fmaf(hb[1], w.y, fmaf(hb[2], w.z, fmaf(hb[3], w.w, bias)))), 0.0f);
    }

    // R13 staging: thread's 4 float4s at half-tile bytes 64*lane + 16j,
    // SW128 swizzle so = o ^ ((o>>3)&0x70); STS.128 at 4-phase minimum.
    unsigned o0 = 64u * lane;
#pragma unroll
    for (int j = 0; j < 4; j++) {
        unsigned o  = o0 + 16u * j;
        unsigned so = o ^ ((o >> 3) & 0x70);
        float4 v = (j == 0) ? make_float4(ya[0], ya[1], ya[2], ya[3])
                 : (j == 1) ? make_float4(ya[4], ya[5], ya[6], ya[7])
                 : (j == 2) ? make_float4(yb[0], yb[1], yb[2], yb[3])
                            : make_float4(yb[4], yb[5], yb[6], yb[7]);
        asm volatile("st.shared.v4.f32 [%0], {%1,%2,%3,%4};"
                     :: "r"(half + so), "f"(v.x), "f"(v.y), "f"(v.z), "f"(v.w)
                     : "memory");
    }
}

// ---------------- R16: TMA tensor-store kernel ------------------------------
__global__ void __launch_bounds__(THREADS)
lse_tma(const float* __restrict__ coords,
        const float* __restrict__ nbr,
        const float* __restrict__ W1, const float* __restrict__ g1,
        const float* __restrict__ b1, const float* __restrict__ m1,
        const float* __restrict__ v1,
        const float* __restrict__ W2, const float* __restrict__ g2,
        const float* __restrict__ b2, const float* __restrict__ m2,
        const float* __restrict__ v2,
        const __grid_constant__ CUtensorMap tmap)
{
    __shared__ __align__(16) float sw[60];
    __shared__ char raw[WARPS * 4096 + 1024];   // over-allocated for 1KB alignment

    int t    = threadIdx.x;
    int warp = t >> 5;
    int lane = t & 31;

    // 2-pt-thread index for pass p: gp = blockIdx*512 + warp*64 + 32p + lane
    int g0 = blockIdx.x * (THREADS * 2) + warp * 64 + lane;

    // ---- Issue pass-0 data loads FIRST (latency overlaps the weight fold) ----
    const float2* nb2 = reinterpret_cast<const float2*>(nbr);
    float2 va = __ldg(nb2 + (size_t)g0 * 3 + 0);
    float2 vb = __ldg(nb2 + (size_t)g0 * 3 + 1);
    float2 vc = __ldg(nb2 + (size_t)g0 * 3 + 2);
    const float* cp0 = coords + (size_t)(g0 >> 3) * 3;
    float c0 = __ldg(cp0 + 0), c1 = __ldg(cp0 + 1), c2 = __ldg(cp0 + 2);

    fold_weights(sw, t, W1, g1, b1, m1, v1, W2, g2, b2, m2, v2);
    __syncthreads();
    const float4* w4 = reinterpret_cast<const float4*>(sw);

    float4 t1v = w4[4];
    const float* t1p = reinterpret_cast<const float*>(&t1v);
    float4 t2a = w4[13], t2b = w4[14];
    const float* t2p0 = reinterpret_cast<const float*>(&t2a);
    const float* t2p1 = reinterpret_cast<const float*>(&t2b);

    unsigned stg  = (smem_u32(raw) + 1023u) & ~1023u;
    unsigned tile = stg + warp * 4096u;        // 4KB per warp, stays 1KB aligned

    // ---- Pass 0: points warpbase .. warpbase+63 -> half-tile at +0 ----
    two_points_pass(va, vb, vc, c0, c1, c2, w4, t1p, t2p0, t2p1, tile, lane);

    // ---- Pass 1: points warpbase+64 .. +127 -> half-tile at +2048 ----
    {
        int g1i = g0 + 32;
        float2 wa = __ldg(nb2 + (size_t)g1i * 3 + 0);
        float2 wb = __ldg(nb2 + (size_t)g1i * 3 + 1);
        float2 wc = __ldg(nb2 + (size_t)g1i * 3 + 2);
        const float* cp1 = coords + (size_t)(g1i >> 3) * 3;
        float d0 = __ldg(cp1 + 0), d1 = __ldg(cp1 + 1), d2 = __ldg(cp1 + 2);
        two_points_pass(wa, wb, wc, d0, d1, d2, w4, t1p, t2p0, t2p1, tile + 2048u, lane);
    }

    asm volatile("fence.proxy.async.shared::cta;" ::: "memory");
    __syncwarp();

    if (lane == 0) {
        int row = (blockIdx.x * WARPS + warp) * 32;   // 32 gmem rows of 128B per warp
        const CUtensorMap* tp = &tmap;
        asm volatile(
            "cp.async.bulk.tensor.2d.global.shared::cta.tile.bulk_group "
            "[%0, {%1, %2}], [%3];"
            :: "l"(tp), "r"(0), "r"(row), "r"(tile) : "memory");
        asm volatile("cp.async.bulk.commit_group;" ::: "memory");
        asm volatile("cp.async.bulk.wait_group.read 0;" ::: "memory");
    }
}

// ---------------- Fallback: R8-style kernel (2 pts/thread, STG path) --------
#define STR 68
__global__ void __launch_bounds__(THREADS)
lse_r8(const float* __restrict__ coords,
       const float* __restrict__ nbr,
       const float* __restrict__ W1, const float* __restrict__ g1,
       const float* __restrict__ b1, const float* __restrict__ m1,
       const float* __restrict__ v1,
       const float* __restrict__ W2, const float* __restrict__ g2,
       const float* __restrict__ b2, const float* __restrict__ m2,
       const float* __restrict__ v2,
       float* __restrict__ out)
{
    __shared__ __align__(16) float sw[60];
    __shared__ __align__(16) float sbuf[WARPS][8][STR];

    int t = threadIdx.x;
    fold_weights(sw, t, W1, g1, b1, m1, v1, W2, g2, b2, m2, v2);
    __syncthreads();
    const float4* w4 = reinterpret_cast<const float4*>(sw);

    float4 t1v = w4[4];
    const float* t1p = reinterpret_cast<const float*>(&t1v);
    float4 t2a = w4[13], t2b = w4[14];
    const float* t2p0 = reinterpret_cast<const float*>(&t2a);
    const float* t2p1 = reinterpret_cast<const float*>(&t2b);

    int g    = blockIdx.x * THREADS + t;
    int warp = t >> 5;
    int lane = t & 31;

    const float2* nb2 = reinterpret_cast<const float2*>(nbr) + (size_t)g * 3;
    float2 va = __ldg(nb2 + 0);
    float2 vb = __ldg(nb2 + 1);
    float2 vc = __ldg(nb2 + 2);
    const float* cp = coords + (size_t)(g >> 3) * 3;
    float c0 = __ldg(cp + 0), c1 = __ldg(cp + 1), c2 = __ldg(cp + 2);

    float ax = va.x - c0, ay = va.y - c1, az = vb.x - c2;
    float bx = vb.y - c0, by = vc.x - c1, bz = vc.y - c2;
    float da = sqrt_ap(fmaf(ax, ax, fmaf(ay, ay, az * az)));
    float db = sqrt_ap(fmaf(bx, bx, fmaf(by, by, bz * bz)));

    float ha[4], hb[4];
#pragma unroll
    for (int o = 0; o < 4; o++) {
        float4 w = w4[o];
        ha[o] = fmaxf(fmaf(ax, w.x, fmaf(ay, w.y, fmaf(az, w.z, fmaf(da, w.w, t1p[o])))), 0.0f);
        hb[o] = fmaxf(fmaf(bx, w.x, fmaf(by, w.y, fmaf(bz, w.z, fmaf(db, w.w, t1p[o])))), 0.0f);
    }
#pragma unroll
    for (int o = 0; o < 8; o++) {
        float4 w = w4[5 + o];
        float bias = (o < 4) ? t2p0[o] : t2p1[o - 4];
        float ya = fmaxf(fmaf(ha[0], w.x, fmaf(ha[1], w.y, fmaf(ha[2], w.z, fmaf(ha[3], w.w, bias)))), 0.0f);
        float yb = fmaxf(fmaf(hb[0], w.x, fmaf(hb[1], w.y, fmaf(hb[2], w.z, fmaf(hb[3], w.w, bias)))), 0.0f);
        *reinterpret_cast<float2*>(&sbuf[warp][o][2 * lane]) = make_float2(ya, yb);
    }
    __syncwarp();

    int warpbase = blockIdx.x * (THREADS * 2) + warp * 64;
    float4* o4 = reinterpret_cast<float4*>(out) + (size_t)warpbase * 2;
#pragma unroll
    for (int k = 0; k < 4; k++) {
        int f  = lane + 32 * k;
        int pt = f >> 1;
        int cb = (f & 1) * 4;
        float4 v;
        v.x = sbuf[warp][cb + 0][pt];
        v.y = sbuf[warp][cb + 1][pt];
        v.z = sbuf[warp][cb + 2][pt];
        v.w = sbuf[warp][cb + 3][pt];
        o4[f] = v;
    }
}

// ---------------- host ------------------------------------------------------
typedef CUresult (*tmap_encode_fn)(
    CUtensorMap*, CUtensorMapDataType, cuuint32_t, void*,
    const cuuint64_t*, const cuuint64_t*, const cuuint32_t*, const cuuint32_t*,
    CUtensorMapInterleave, CUtensorMapSwizzle, CUtensorMapL2promotion,
    CUtensorMapFloatOOBfill);

extern "C" void kernel_launch(void* const* d_in, const int* in_sizes, int n_in,
                              void* d_out, int out_size)
{
    const float* coords = (const float*)d_in[0];
    const float* nbr    = (const float*)d_in[1];
    const float* W1     = (const float*)d_in[2];
    const float* g1     = (const float*)d_in[3];
    const float* b1     = (const float*)d_in[4];
    const float* m1     = (const float*)d_in[5];
    const float* v1     = (const float*)d_in[6];
    const float* W2     = (const float*)d_in[7];
    const float* g2     = (const float*)d_in[8];
    const float* b2     = (const float*)d_in[9];
    const float* m2     = (const float*)d_in[10];
    const float* v2     = (const float*)d_in[11];
    float* out = (float*)d_out;

    tmap_encode_fn encode = nullptr;
    cudaDriverEntryPointQueryResult qr = cudaDriverEntryPointSymbolNotFound;
#if CUDART_VERSION >= 12050
    cudaGetDriverEntryPointByVersion("cuTensorMapEncodeTiled", (void**)&encode,
                                     12000, cudaEnableDefault, &qr);
#else
    cudaGetDriverEntryPoint("cuTensorMapEncodeTiled", (void**)&encode,
                            cudaEnableDefault, &qr);
#endif

    bool tma_ok = false;
    CUtensorMap tmap;
    if (encode && qr == cudaDriverEntryPointSuccess) {
        cuuint64_t dims[2]    = {32, (cuuint64_t)TOTAL * 32 / 128};  // 524288 rows
        cuuint64_t strides[1] = {128};
        cuuint32_t box[2]     = {32, 32};     // one warp tile: 32 rows x 128B = 4KB
        cuuint32_t es[2]      = {1, 1};
        CUresult r = encode(&tmap, CU_TENSOR_MAP_DATA_TYPE_FLOAT32, 2, out,
                            dims, strides, box, es,
                            CU_TENSOR_MAP_INTERLEAVE_NONE,
                            CU_TENSOR_MAP_SWIZZLE_128B,
                            CU_TENSOR_MAP_L2_PROMOTION_L2_128B,
                            CU_TENSOR_MAP_FLOAT_OOB_FILL_NONE);
        tma_ok = (r == CUDA_SUCCESS);
    }

    if (tma_ok) {
        int blocks = TOTAL / (THREADS * 4);   // 2048 (4 pts/thread via 2 passes)
        lse_tma<<<blocks, THREADS>>>(coords, nbr, W1, g1, b1, m1, v1,
                                     W2, g2, b2, m2, v2, tmap);
    } else {
        int blocks = TOTAL / (THREADS * 2);   // 4096
        lse_r8<<<blocks, THREADS>>>(coords, nbr, W1, g1, b1, m1, v1,
                                    W2, g2, b2, m2, v2, out);
    }
}

// round 17
// speedup vs baseline: 1.1488x; 1.0363x over previous
#include <cuda_runtime.h>
#include <cuda.h>

// LocalSpatialEncoding: enc=[rel(3),|rel|] -> (W1,BN,ReLU)[4] -> (W2,BN,ReLU)[8]
// B=8,N=16384,K=16. Output (B,N,K,8) fp32.
// R17 (= R13 + two register-safe tweaks):
//   1. __launch_bounds__(256, 8): force 32 regs -> 8 CTAs/SM (R13 was 34 regs
//      -> 7 CTAs, register-limited).
//   2. data LDGs issued before the weight fold (latency overlap; proven
//      harmless in R16).
// Architecture: 2 pts/thread, per-warp SW128 2KB stage (STS.128 minimal
// 4 phases) + one cp.async.bulk.tensor.2d store per warp.
// Fallback: R8-style kernel if tensor-map encode is unavailable.

#define LSE_EPS 1e-5f
#define TOTAL   (8 * 16384 * 16)   // 2097152 points
#define THREADS 256
#define WARPS   8

__device__ __forceinline__ float sqrt_ap(float x) {
    float r; asm("sqrt.approx.f32 %0,%1;" : "=f"(r) : "f"(x)); return r;
}
__device__ __forceinline__ unsigned smem_u32(const void* p) {
    unsigned a;
    asm("{ .reg .u64 t; cvta.to.shared.u64 t, %1; cvt.u32.u64 %0, t; }"
        : "=r"(a) : "l"(p));
    return a;
}

__device__ __forceinline__ void fold_weights(
    float* sw, int t,
    const float* W1, const float* g1, const float* b1, const float* m1, const float* v1,
    const float* W2, const float* g2, const float* b2, const float* m2, const float* v2)
{
    if (t < 16) {
        int o = t >> 2;
        float s = g1[o] * rsqrtf(v1[o] + LSE_EPS);
        sw[t] = W1[t] * s;
        if ((t & 3) == 0) sw[16 + o] = b1[o] - m1[o] * s;
    } else if (t < 48) {
        int i = t - 16;
        int o = i >> 2;
        float s = g2[o] * rsqrtf(v2[o] + LSE_EPS);
        sw[20 + i] = W2[i] * s;
        if ((i & 3) == 0) sw[52 + o] = b2[o] - m2[o] * s;
    }
}

// ---------------- R17: TMA tensor-store kernel ------------------------------
__global__ void __launch_bounds__(THREADS, 8)
lse_tma(const float* __restrict__ coords,
        const float* __restrict__ nbr,
        const float* __restrict__ W1, const float* __restrict__ g1,
        const float* __restrict__ b1, const float* __restrict__ m1,
        const float* __restrict__ v1,
        const float* __restrict__ W2, const float* __restrict__ g2,
        const float* __restrict__ b2, const float* __restrict__ m2,
        const float* __restrict__ v2,
        const __grid_constant__ CUtensorMap tmap)
{
    __shared__ __align__(16) float sw[60];
    __shared__ char raw[WARPS * 2048 + 1024];   // over-allocated for 1KB alignment

    int t    = threadIdx.x;
    int g    = blockIdx.x * THREADS + t;   // thread owns points 2g, 2g+1
    int warp = t >> 5;
    int lane = t & 31;

    // ---- Data loads first: latency overlaps the weight fold ----
    const float2* nb2 = reinterpret_cast<const float2*>(nbr) + (size_t)g * 3;
    float2 va = __ldg(nb2 + 0);
    float2 vb = __ldg(nb2 + 1);
    float2 vc = __ldg(nb2 + 2);

    const float* cp = coords + (size_t)(g >> 3) * 3;
    float c0 = __ldg(cp + 0), c1 = __ldg(cp + 1), c2 = __ldg(cp + 2);

    fold_weights(sw, t, W1, g1, b1, m1, v1, W2, g2, b2, m2, v2);
    __syncthreads();
    const float4* w4 = reinterpret_cast<const float4*>(sw);

    // pt0 = (va.x, va.y, vb.x), pt1 = (vb.y, vc.x, vc.y)
    float ax = va.x - c0, ay = va.y - c1, az = vb.x - c2;
    float bx = vb.y - c0, by = vc.x - c1, bz = vc.y - c2;
    float da = sqrt_ap(fmaf(ax, ax, fmaf(ay, ay, az * az)));
    float db = sqrt_ap(fmaf(bx, bx, fmaf(by, by, bz * bz)));

    float4 t1v = w4[4];
    const float* t1p = reinterpret_cast<const float*>(&t1v);
    float ha[4], hb[4];
#pragma unroll
    for (int o = 0; o < 4; o++) {
        float4 w = w4[o];
        ha[o] = fmaxf(fmaf(ax, w.x, fmaf(ay, w.y, fmaf(az, w.z, fmaf(da, w.w, t1p[o])))), 0.0f);
        hb[o] = fmaxf(fmaf(bx, w.x, fmaf(by, w.y, fmaf(bz, w.z, fmaf(db, w.w, t1p[o])))), 0.0f);
    }

    float4 t2a = w4[13], t2b = w4[14];
    const float* t2p0 = reinterpret_cast<const float*>(&t2a);
    const float* t2p1 = reinterpret_cast<const float*>(&t2b);
    float ya[8], yb[8];
#pragma unroll
    for (int o = 0; o < 8; o++) {
        float4 w = w4[5 + o];
        float bias = (o < 4) ? t2p0[o] : t2p1[o - 4];
        ya[o] = fmaxf(fmaf(ha[0], w.x, fmaf(ha[1], w.y, fmaf(ha[2], w.z, fmaf(ha[3], w.w, bias)))), 0.0f);
        yb[o] = fmaxf(fmaf(hb[0], w.x, fmaf(hb[1], w.y, fmaf(hb[2], w.z, fmaf(hb[3], w.w, bias)))), 0.0f);
    }

    // 1024B-aligned stage base; warp tile = 2KB (stays 1KB aligned).
    unsigned stg  = (smem_u32(raw) + 1023u) & ~1023u;
    unsigned tile = stg + warp * 2048u;

    // Stage in FINAL layout + SW128 swizzle. Thread's 4 float4s at bytes
    // 64*lane + 16j; swizzled STS.128 is 4-phase (minimal).
    unsigned o0 = 64u * lane;
#pragma unroll
    for (int j = 0; j < 4; j++) {
        unsigned o  = o0 + 16u * j;
        unsigned so = o ^ ((o >> 3) & 0x70);
        float4 v = (j == 0) ? make_float4(ya[0], ya[1], ya[2], ya[3])
                 : (j == 1) ? make_float4(ya[4], ya[5], ya[6], ya[7])
                 : (j == 2) ? make_float4(yb[0], yb[1], yb[2], yb[3])
                            : make_float4(yb[4], yb[5], yb[6], yb[7]);
        asm volatile("st.shared.v4.f32 [%0], {%1,%2,%3,%4};"
                     :: "r"(tile + so), "f"(v.x), "f"(v.y), "f"(v.z), "f"(v.w)
                     : "memory");
    }

    asm volatile("fence.proxy.async.shared::cta;" ::: "memory");
    __syncwarp();

    if (lane == 0) {
        int row = (blockIdx.x * WARPS + warp) * 16;   // 16 gmem rows of 128B per warp
        const CUtensorMap* tp = &tmap;
        asm volatile(
            "cp.async.bulk.tensor.2d.global.shared::cta.tile.bulk_group "
            "[%0, {%1, %2}], [%3];"
            :: "l"(tp), "r"(0), "r"(row), "r"(tile) : "memory");
        asm volatile("cp.async.bulk.commit_group;" ::: "memory");
        asm volatile("cp.async.bulk.wait_group.read 0;" ::: "memory");
    }
}

// ---------------- Fallback: R8-style kernel (2 pts/thread, STG path) --------
#define STR 68
__global__ void __launch_bounds__(THREADS)
lse_r8(const float* __restrict__ coords,
       const float* __restrict__ nbr,
       const float* __restrict__ W1, const float* __restrict__ g1,
       const float* __restrict__ b1, const float* __restrict__ m1,
       const float* __restrict__ v1,
       const float* __restrict__ W2, const float* __restrict__ g2,
       const float* __restrict__ b2, const float* __restrict__ m2,
       const float* __restrict__ v2,
       float* __restrict__ out)
{
    __shared__ __align__(16) float sw[60];
    __shared__ __align__(16) float sbuf[WARPS][8][STR];

    int t = threadIdx.x;
    fold_weights(sw, t, W1, g1, b1, m1, v1, W2, g2, b2, m2, v2);
    __syncthreads();
    const float4* w4 = reinterpret_cast<const float4*>(sw);

    float4 t1v = w4[4];
    const float* t1p = reinterpret_cast<const float*>(&t1v);
    float4 t2a = w4[13], t2b = w4[14];
    const float* t2p0 = reinterpret_cast<const float*>(&t2a);
    const float* t2p1 = reinterpret_cast<const float*>(&t2b);

    int g    = blockIdx.x * THREADS + t;
    int warp = t >> 5;
    int lane = t & 31;

    const float2* nb2 = reinterpret_cast<const float2*>(nbr) + (size_t)g * 3;
    float2 va = __ldg(nb2 + 0);
    float2 vb = __ldg(nb2 + 1);
    float2 vc = __ldg(nb2 + 2);
    const float* cp = coords + (size_t)(g >> 3) * 3;
    float c0 = __ldg(cp + 0), c1 = __ldg(cp + 1), c2 = __ldg(cp + 2);

    float ax = va.x - c0, ay = va.y - c1, az = vb.x - c2;
    float bx = vb.y - c0, by = vc.x - c1, bz = vc.y - c2;
    float da = sqrt_ap(fmaf(ax, ax, fmaf(ay, ay, az * az)));
    float db = sqrt_ap(fmaf(bx, bx, fmaf(by, by, bz * bz)));

    float ha[4], hb[4];
#pragma unroll
    for (int o = 0; o < 4; o++) {
        float4 w = w4[o];
        ha[o] = fmaxf(fmaf(ax, w.x, fmaf(ay, w.y, fmaf(az, w.z, fmaf(da, w.w, t1p[o])))), 0.0f);
        hb[o] = fmaxf(fmaf(bx, w.x, fmaf(by, w.y, fmaf(bz, w.z, fmaf(db, w.w, t1p[o])))), 0.0f);
    }
#pragma unroll
    for (int o = 0; o < 8; o++) {
        float4 w = w4[5 + o];
        float bias = (o < 4) ? t2p0[o] : t2p1[o - 4];
        float ya = fmaxf(fmaf(ha[0], w.x, fmaf(ha[1], w.y, fmaf(ha[2], w.z, fmaf(ha[3], w.w, bias)))), 0.0f);
        float yb = fmaxf(fmaf(hb[0], w.x, fmaf(hb[1], w.y, fmaf(hb[2], w.z, fmaf(hb[3], w.w, bias)))), 0.0f);
        *reinterpret_cast<float2*>(&sbuf[warp][o][2 * lane]) = make_float2(ya, yb);
    }
    __syncwarp();

    int warpbase = blockIdx.x * (THREADS * 2) + warp * 64;
    float4* o4 = reinterpret_cast<float4*>(out) + (size_t)warpbase * 2;
#pragma unroll
    for (int k = 0; k < 4; k++) {
        int f  = lane + 32 * k;
        int pt = f >> 1;
        int cb = (f & 1) * 4;
        float4 v;
        v.x = sbuf[warp][cb + 0][pt];
        v.y = sbuf[warp][cb + 1][pt];
        v.z = sbuf[warp][cb + 2][pt];
        v.w = sbuf[warp][cb + 3][pt];
        o4[f] = v;
    }
}

// ---------------- host ------------------------------------------------------
typedef CUresult (*tmap_encode_fn)(
    CUtensorMap*, CUtensorMapDataType, cuuint32_t, void*,
    const cuuint64_t*, const cuuint64_t*, const cuuint32_t*, const cuuint32_t*,
    CUtensorMapInterleave, CUtensorMapSwizzle, CUtensorMapL2promotion,
    CUtensorMapFloatOOBfill);

extern "C" void kernel_launch(void* const* d_in, const int* in_sizes, int n_in,
                              void* d_out, int out_size)
{
    const float* coords = (const float*)d_in[0];
    const float* nbr    = (const float*)d_in[1];
    const float* W1     = (const float*)d_in[2];
    const float* g1     = (const float*)d_in[3];
    const float* b1     = (const float*)d_in[4];
    const float* m1     = (const float*)d_in[5];
    const float* v1     = (const float*)d_in[6];
    const float* W2     = (const float*)d_in[7];
    const float* g2     = (const float*)d_in[8];
    const float* b2     = (const float*)d_in[9];
    const float* m2     = (const float*)d_in[10];
    const float* v2     = (const float*)d_in[11];
    float* out = (float*)d_out;

    int blocks = TOTAL / (THREADS * 2);   // 4096

    tmap_encode_fn encode = nullptr;
    cudaDriverEntryPointQueryResult qr = cudaDriverEntryPointSymbolNotFound;
#if CUDART_VERSION >= 12050
    cudaGetDriverEntryPointByVersion("cuTensorMapEncodeTiled", (void**)&encode,
                                     12000, cudaEnableDefault, &qr);
#else
    cudaGetDriverEntryPoint("cuTensorMapEncodeTiled", (void**)&encode,
                            cudaEnableDefault, &qr);
#endif

    bool tma_ok = false;
    CUtensorMap tmap;
    if (encode && qr == cudaDriverEntryPointSuccess) {
        // Output viewed as [32 floats][524288 rows], 128B rows, SW128.
        cuuint64_t dims[2]    = {32, (cuuint64_t)TOTAL * 32 / 128};  // 524288 rows
        cuuint64_t strides[1] = {128};
        cuuint32_t box[2]     = {32, 16};     // one warp tile: 16 rows x 128B = 2KB
        cuuint32_t es[2]      = {1, 1};
        CUresult r = encode(&tmap, CU_TENSOR_MAP_DATA_TYPE_FLOAT32, 2, out,
                            dims, strides, box, es,
                            CU_TENSOR_MAP_INTERLEAVE_NONE,
                            CU_TENSOR_MAP_SWIZZLE_128B,
                            CU_TENSOR_MAP_L2_PROMOTION_L2_128B,
                            CU_TENSOR_MAP_FLOAT_OOB_FILL_NONE);
        tma_ok = (r == CUDA_SUCCESS);
    }

    if (tma_ok) {
        lse_tma<<<blocks, THREADS>>>(coords, nbr, W1, g1, b1, m1, v1,
                                     W2, g2, b2, m2, v2, tmap);
    } else {
        lse_r8<<<blocks, THREADS>>>(coords, nbr, W1, g1, b1, m1, v1,
                                    W2, g2, b2, m2, v2, out);
    }
}